// round 4
// baseline (speedup 1.0000x reference)
#include <cuda_runtime.h>

// Problem constants (fixed by dataset)
#define D_MODEL 1024
#define ADAPT   128
#define NUM_LIB 8
#define NPAIR   (NUM_LIB * NUM_LIB)   // 64
#define MAXB    1024
#define KC      8                      // K-split for gemm1
#define KCH     (D_MODEL / KC)         // 128
#define RT      16                     // row tile

typedef unsigned long long ull;

// Packed fp32x2 FMA (sm_10x): d = a*b + c per 32-bit lane
#define FMA2(d, a, b, c) \
    asm("fma.rn.f32x2 %0, %1, %2, %3;" : "=l"(d) : "l"(a), "l"(b), "l"(c))
#define ADD2(d, a, b) \
    asm("add.rn.f32x2 %0, %1, %2;" : "=l"(d) : "l"(a), "l"(b))
#define PACK2(d, s) \
    asm("mov.b64 %0, {%1, %1};" : "=l"(d) : "f"(s))

// Device scratch (no allocations allowed)
__device__ int   g_off[NPAIR + 1];
__device__ int   g_rows[MAXB];
__device__ float g_hp[KC][MAXB * ADAPT];   // partial pre-activation sums (4 MB)

// ---------------------------------------------------------------------------
// Build per-pair CSR of row indices. One CTA, 1024 threads.
// ---------------------------------------------------------------------------
__global__ void k_build(const int* __restrict__ src, const int* __restrict__ tgt, int B) {
    __shared__ int cnt[NPAIR];
    __shared__ int off[NPAIR + 1];
    int t = threadIdx.x;
    if (t < NPAIR) cnt[t] = 0;
    __syncthreads();
    int p = -1, slot = 0;
    if (t < B) {
        int s = src[t], g = tgt[t];
        if (s != g) {
            p = s * NUM_LIB + g;
            slot = atomicAdd(&cnt[p], 1);
        }
    }
    __syncthreads();
    if (t == 0) {
        int acc = 0;
        for (int i = 0; i < NPAIR; i++) { off[i] = acc; acc += cnt[i]; }
        off[NPAIR] = acc;
    }
    __syncthreads();
    if (t <= NPAIR) g_off[t] = off[t];
    if (p >= 0) g_rows[off[p] + slot] = t;
}

// ---------------------------------------------------------------------------
// Identity rows: out[b] = x[b]. 128 CTAs x 256 thr, grid-stride over rows.
// ---------------------------------------------------------------------------
__global__ void __launch_bounds__(256)
k_copy(const float* __restrict__ x,
       const int* __restrict__ src, const int* __restrict__ tgt,
       float* __restrict__ out, int B) {
    for (int b = blockIdx.x; b < B; b += gridDim.x) {
        if (src[b] != tgt[b]) continue;
        const float4* xi = (const float4*)(x + (size_t)b * D_MODEL);
        float4* yo = (float4*)(out + (size_t)b * D_MODEL);
        yo[threadIdx.x] = xi[threadIdx.x];
    }
}

// ---------------------------------------------------------------------------
// GEMM1 (K-split): g_hp[kz][row, a] = x[row, kz*128:+128] . W1[p, slice, a]
// grid (NPAIR, KC), 256 thr. tx = t&31 -> a-quad (a0 = tx*4, packed pairs),
// rg = t>>5 -> rows {2rg, 2rg+1}. x duplicated in smem as f32x2: zero MOVs.
// ---------------------------------------------------------------------------
__global__ void __launch_bounds__(256, 4)
k_gemm1(const float* __restrict__ x, const float* __restrict__ W1) {
    __shared__ ull xs2[KCH * RT];        // 16 KB, [k][r] duplicated pairs
    int p  = blockIdx.x;
    int kz = blockIdx.y;
    int begin = g_off[p], end = g_off[p + 1];
    int t  = threadIdx.x;
    int tx = t & 31;
    int rg = t >> 5;
    int a0 = tx * 4;
    const float* Wp = W1 + ((size_t)p * D_MODEL + (size_t)kz * KCH) * ADAPT + a0;
    float* hp = g_hp[kz];

    // staging map: each thread owns one row r = t&15, 8 k-values
    int rs  = t & 15;
    int kb  = t >> 4;

    for (int base = begin; base < end; base += RT) {
        int n = min(RT, end - base);
        __syncthreads();                 // previous tile done with xs2
        {
            const float* xrow = (rs < n)
                ? x + (size_t)g_rows[base + rs] * D_MODEL + kz * KCH : 0;
            #pragma unroll
            for (int j = 0; j < KCH / 16; j++) {   // 8 iters
                int k = kb + 16 * j;
                float v = (rs < n) ? xrow[k] : 0.f;
                ull vd; PACK2(vd, v);
                xs2[k * RT + rs] = vd;
            }
        }
        __syncthreads();

        ull a00 = 0, a01 = 0, a10 = 0, a11 = 0;  // [apair][row]
        ulonglong2 wv = *(const ulonglong2*)(Wp);
        #pragma unroll 4
        for (int k = 0; k < KCH; k++) {
            ulonglong2 wc = wv;
            if (k + 1 < KCH)
                wv = *(const ulonglong2*)(Wp + (size_t)(k + 1) * ADAPT);
            ull x0 = xs2[k * RT + 2 * rg];
            ull x1 = xs2[k * RT + 2 * rg + 1];
            FMA2(a00, wc.x, x0, a00);
            FMA2(a01, wc.x, x1, a01);
            FMA2(a10, wc.y, x0, a10);
            FMA2(a11, wc.y, x1, a11);
        }
        int r0 = 2 * rg, r1 = 2 * rg + 1;
        if (r0 < n) {
            float* o = hp + (size_t)g_rows[base + r0] * ADAPT + a0;
            *(ull*)o = a00; *(ull*)(o + 2) = a10;
        }
        if (r1 < n) {
            float* o = hp + (size_t)g_rows[base + r1] * ADAPT + a0;
            *(ull*)o = a01; *(ull*)(o + 2) = a11;
        }
    }
}

// ---------------------------------------------------------------------------
// GEMM2: out[row, d] = relu(sum_kz g_hp + b1) . W2[p,:,d] + b2[p,d]
// grid (NPAIR, 8), 256 thr. tx = t&31 -> d-quad (d0 = dc*128 + tx*4),
// rg = t>>5 -> rows {2rg, 2rg+1}. h duplicated in smem as f32x2.
// ---------------------------------------------------------------------------
__global__ void __launch_bounds__(256, 4)
k_gemm2(const float* __restrict__ W2, const float* __restrict__ b1,
        const float* __restrict__ b2, float* __restrict__ out) {
    __shared__ ull hs2[ADAPT * RT];      // 16 KB, [aa][r] duplicated pairs
    int p  = blockIdx.x;
    int dc = blockIdx.y;
    int begin = g_off[p], end = g_off[p + 1];
    int t  = threadIdx.x;
    int tx = t & 31;
    int rg = t >> 5;
    int d0 = dc * 128 + tx * 4;
    const float* Wp = W2 + (size_t)p * ADAPT * D_MODEL + d0;
    ulonglong2 bb = *(const ulonglong2*)(b2 + (size_t)p * D_MODEL + d0);

    int rs = t & 15;
    int ab = t >> 4;

    for (int base = begin; base < end; base += RT) {
        int n = min(RT, end - base);
        __syncthreads();                 // previous tile done with hs2
        {
            size_t rowoff = (rs < n) ? (size_t)g_rows[base + rs] * ADAPT : 0;
            #pragma unroll
            for (int j = 0; j < ADAPT / 16; j++) {   // 8 iters
                int aa = ab + 16 * j;
                float v = 0.f;
                if (rs < n) {
                    size_t idx = rowoff + aa;
                    float s0 = g_hp[0][idx] + g_hp[1][idx];
                    float s1 = g_hp[2][idx] + g_hp[3][idx];
                    float s2 = g_hp[4][idx] + g_hp[5][idx];
                    float s3 = g_hp[6][idx] + g_hp[7][idx];
                    v = fmaxf((s0 + s1) + (s2 + s3) + b1[p * ADAPT + aa], 0.f);
                }
                ull vd; PACK2(vd, v);
                hs2[aa * RT + rs] = vd;
            }
        }
        __syncthreads();

        ull a00 = 0, a01 = 0, a10 = 0, a11 = 0;  // [dpair][row]
        ulonglong2 wv = *(const ulonglong2*)(Wp);
        #pragma unroll 4
        for (int aa = 0; aa < ADAPT; aa++) {
            ulonglong2 wc = wv;
            if (aa + 1 < ADAPT)
                wv = *(const ulonglong2*)(Wp + (size_t)(aa + 1) * D_MODEL);
            ull h0 = hs2[aa * RT + 2 * rg];
            ull h1 = hs2[aa * RT + 2 * rg + 1];
            FMA2(a00, wc.x, h0, a00);
            FMA2(a01, wc.x, h1, a01);
            FMA2(a10, wc.y, h0, a10);
            FMA2(a11, wc.y, h1, a11);
        }
        ADD2(a00, a00, bb.x); ADD2(a10, a10, bb.y);
        ADD2(a01, a01, bb.x); ADD2(a11, a11, bb.y);
        int r0 = 2 * rg, r1 = 2 * rg + 1;
        if (r0 < n) {
            float* o = out + (size_t)g_rows[base + r0] * D_MODEL + d0;
            *(ull*)o = a00; *(ull*)(o + 2) = a10;
        }
        if (r1 < n) {
            float* o = out + (size_t)g_rows[base + r1] * D_MODEL + d0;
            *(ull*)o = a01; *(ull*)(o + 2) = a11;
        }
    }
}

// ---------------------------------------------------------------------------
extern "C" void kernel_launch(void* const* d_in, const int* in_sizes, int n_in,
                              void* d_out, int out_size) {
    const float* x   = (const float*)d_in[0];
    const int*   src = (const int*)d_in[1];
    const int*   tgt = (const int*)d_in[2];
    const float* W1  = (const float*)d_in[3];
    const float* b1  = (const float*)d_in[4];
    const float* W2  = (const float*)d_in[5];
    const float* b2  = (const float*)d_in[6];
    float* out = (float*)d_out;
    int B = in_sizes[1];  // 1024

    k_build<<<1, 1024>>>(src, tgt, B);
    k_copy<<<128, 256>>>(x, src, tgt, out, B);
    k_gemm1<<<dim3(NPAIR, KC), 256>>>(x, W1);
    k_gemm2<<<dim3(NPAIR, 8), 256>>>(W2, b1, b2, out);
}

// round 5
// speedup vs baseline: 1.0633x; 1.0633x over previous
#include <cuda_runtime.h>

// Problem constants (fixed by dataset)
#define D_MODEL 1024
#define ADAPT   128
#define NUM_LIB 8
#define NPAIR   (NUM_LIB * NUM_LIB)   // 64
#define MAXB    1024
#define KC      8                      // K-split for gemm1
#define KCH     (D_MODEL / KC)         // 128
#define RT      16                     // row tile

typedef unsigned long long ull;

// Packed fp32x2 ops (sm_10x)
#define FMA2(d, a, b, c) \
    asm("fma.rn.f32x2 %0, %1, %2, %3;" : "=l"(d) : "l"(a), "l"(b), "l"(c))
#define ADD2(d, a, b) \
    asm("add.rn.f32x2 %0, %1, %2;" : "=l"(d) : "l"(a), "l"(b))
#define PACK2(d, s) \
    asm("mov.b64 %0, {%1, %1};" : "=l"(d) : "f"(s))

// Device scratch (no allocations allowed)
__device__ int   g_off[NPAIR + 1];
__device__ int   g_rows[MAXB];
__device__ float g_hp[KC][MAXB * ADAPT];   // partial pre-activation sums (4 MB)

// ---------------------------------------------------------------------------
// Build per-pair CSR of row indices. One CTA, 1024 threads.
// ---------------------------------------------------------------------------
__global__ void k_build(const int* __restrict__ src, const int* __restrict__ tgt, int B) {
    __shared__ int cnt[NPAIR];
    __shared__ int off[NPAIR + 1];
    int t = threadIdx.x;
    if (t < NPAIR) cnt[t] = 0;
    __syncthreads();
    int p = -1, slot = 0;
    if (t < B) {
        int s = src[t], g = tgt[t];
        if (s != g) {
            p = s * NUM_LIB + g;
            slot = atomicAdd(&cnt[p], 1);
        }
    }
    __syncthreads();
    if (t == 0) {
        int acc = 0;
        for (int i = 0; i < NPAIR; i++) { off[i] = acc; acc += cnt[i]; }
        off[NPAIR] = acc;
    }
    __syncthreads();
    if (t <= NPAIR) g_off[t] = off[t];
    if (p >= 0) g_rows[off[p] + slot] = t;
}

// ---------------------------------------------------------------------------
// Identity rows: out[b] = x[b]. 128 CTAs x 256 thr, grid-stride over rows.
// ---------------------------------------------------------------------------
__global__ void __launch_bounds__(256)
k_copy(const float* __restrict__ x,
       const int* __restrict__ src, const int* __restrict__ tgt,
       float* __restrict__ out, int B) {
    for (int b = blockIdx.x; b < B; b += gridDim.x) {
        if (src[b] != tgt[b]) continue;
        const float4* xi = (const float4*)(x + (size_t)b * D_MODEL);
        float4* yo = (float4*)(out + (size_t)b * D_MODEL);
        yo[threadIdx.x] = xi[threadIdx.x];
    }
}

// ---------------------------------------------------------------------------
// GEMM1 (K-split): g_hp[kz][row, a] = x[row, kz*128:+128] . W1[p, slice, a]
// grid (NPAIR, KC), 256 thr. tx = t&31 -> a-quad a0 = tx*4 (2 packed pairs via
// one LDG.128); rg = t>>5 -> row pair {2rg, 2rg+1} (one LDS.128 of dup pairs).
// Inner: 4 independent LDG.128 + 4 LDS.128 + 16 FMA2 per 4 k-steps.
// ---------------------------------------------------------------------------
__global__ void __launch_bounds__(256, 4)
k_gemm1(const float* __restrict__ x, const float* __restrict__ W1) {
    __shared__ ull xs2[KCH * RT];        // 16 KB, [k][r] duplicated pairs
    int p  = blockIdx.x;
    int kz = blockIdx.y;
    int begin = g_off[p], end = g_off[p + 1];
    int t  = threadIdx.x;
    int tx = t & 31;
    int rg = t >> 5;
    int a0 = tx * 4;
    const float* Wp = W1 + ((size_t)p * D_MODEL + (size_t)kz * KCH) * ADAPT + a0;
    float* hp = g_hp[kz];

    // staging map: row rs = t>>4 (16 rows), k block k0 = (t&15)*8
    int rs = t >> 4;
    int k0 = (t & 15) * 8;

    for (int base = begin; base < end; base += RT) {
        int n = min(RT, end - base);
        __syncthreads();                 // previous tile done with xs2
        {
            float v[8] = {0,0,0,0,0,0,0,0};
            if (rs < n) {
                const float4* xr = (const float4*)
                    (x + (size_t)g_rows[base + rs] * D_MODEL + kz * KCH + k0);
                float4 u0 = xr[0], u1 = xr[1];
                v[0]=u0.x; v[1]=u0.y; v[2]=u0.z; v[3]=u0.w;
                v[4]=u1.x; v[5]=u1.y; v[6]=u1.z; v[7]=u1.w;
            }
            #pragma unroll
            for (int i = 0; i < 8; i++) {
                ull vd; PACK2(vd, v[i]);
                xs2[(k0 + i) * RT + rs] = vd;
            }
        }
        __syncthreads();

        ull a00 = 0, a01 = 0, a10 = 0, a11 = 0;   // [apair][row]
        const ull* xb = xs2 + 2 * rg;
        #pragma unroll 1
        for (int k = 0; k < KCH; k += 4) {
            ulonglong2 w0 = *(const ulonglong2*)(Wp + (size_t)(k + 0) * ADAPT);
            ulonglong2 w1 = *(const ulonglong2*)(Wp + (size_t)(k + 1) * ADAPT);
            ulonglong2 w2 = *(const ulonglong2*)(Wp + (size_t)(k + 2) * ADAPT);
            ulonglong2 w3 = *(const ulonglong2*)(Wp + (size_t)(k + 3) * ADAPT);
            ulonglong2 x0 = *(const ulonglong2*)(xb + (k + 0) * RT);
            ulonglong2 x1 = *(const ulonglong2*)(xb + (k + 1) * RT);
            ulonglong2 x2 = *(const ulonglong2*)(xb + (k + 2) * RT);
            ulonglong2 x3 = *(const ulonglong2*)(xb + (k + 3) * RT);
            FMA2(a00, w0.x, x0.x, a00); FMA2(a01, w0.x, x0.y, a01);
            FMA2(a10, w0.y, x0.x, a10); FMA2(a11, w0.y, x0.y, a11);
            FMA2(a00, w1.x, x1.x, a00); FMA2(a01, w1.x, x1.y, a01);
            FMA2(a10, w1.y, x1.x, a10); FMA2(a11, w1.y, x1.y, a11);
            FMA2(a00, w2.x, x2.x, a00); FMA2(a01, w2.x, x2.y, a01);
            FMA2(a10, w2.y, x2.x, a10); FMA2(a11, w2.y, x2.y, a11);
            FMA2(a00, w3.x, x3.x, a00); FMA2(a01, w3.x, x3.y, a01);
            FMA2(a10, w3.y, x3.x, a10); FMA2(a11, w3.y, x3.y, a11);
        }
        int r0 = 2 * rg, r1 = 2 * rg + 1;
        if (r0 < n) {
            ulonglong2 s; s.x = a00; s.y = a10;
            *(ulonglong2*)(hp + (size_t)g_rows[base + r0] * ADAPT + a0) = s;
        }
        if (r1 < n) {
            ulonglong2 s; s.x = a01; s.y = a11;
            *(ulonglong2*)(hp + (size_t)g_rows[base + r1] * ADAPT + a0) = s;
        }
    }
}

// ---------------------------------------------------------------------------
// GEMM2: out[row, d] = relu(sum_kz g_hp + b1) . W2[p,:,d] + b2[p,d]
// grid (NPAIR, 8), 256 thr. tx -> d-quad d0 = dc*128 + tx*4; rg -> row pair.
// ---------------------------------------------------------------------------
__global__ void __launch_bounds__(256, 4)
k_gemm2(const float* __restrict__ W2, const float* __restrict__ b1,
        const float* __restrict__ b2, float* __restrict__ out) {
    __shared__ ull hs2[ADAPT * RT];      // 16 KB, [aa][r] duplicated pairs
    int p  = blockIdx.x;
    int dc = blockIdx.y;
    int begin = g_off[p], end = g_off[p + 1];
    int t  = threadIdx.x;
    int tx = t & 31;
    int rg = t >> 5;
    int d0 = dc * 128 + tx * 4;
    const float* Wp = W2 + (size_t)p * ADAPT * D_MODEL + d0;
    ulonglong2 bb = *(const ulonglong2*)(b2 + (size_t)p * D_MODEL + d0);

    // staging map: row rs = t>>4, a block a0s = (t&15)*8
    int rs  = t >> 4;
    int a0s = (t & 15) * 8;

    for (int base = begin; base < end; base += RT) {
        int n = min(RT, end - base);
        __syncthreads();                 // previous tile done with hs2
        {
            float v[8] = {0,0,0,0,0,0,0,0};
            if (rs < n) {
                size_t ro = (size_t)g_rows[base + rs] * ADAPT + a0s;
                #pragma unroll
                for (int kz = 0; kz < KC; kz++) {
                    const float4* hp4 = (const float4*)(g_hp[kz] + ro);
                    float4 u0 = hp4[0], u1 = hp4[1];
                    v[0]+=u0.x; v[1]+=u0.y; v[2]+=u0.z; v[3]+=u0.w;
                    v[4]+=u1.x; v[5]+=u1.y; v[6]+=u1.z; v[7]+=u1.w;
                }
                const float4* bp4 = (const float4*)(b1 + p * ADAPT + a0s);
                float4 c0 = bp4[0], c1 = bp4[1];
                v[0]=fmaxf(v[0]+c0.x,0.f); v[1]=fmaxf(v[1]+c0.y,0.f);
                v[2]=fmaxf(v[2]+c0.z,0.f); v[3]=fmaxf(v[3]+c0.w,0.f);
                v[4]=fmaxf(v[4]+c1.x,0.f); v[5]=fmaxf(v[5]+c1.y,0.f);
                v[6]=fmaxf(v[6]+c1.z,0.f); v[7]=fmaxf(v[7]+c1.w,0.f);
            }
            #pragma unroll
            for (int i = 0; i < 8; i++) {
                ull vd; PACK2(vd, v[i]);
                hs2[(a0s + i) * RT + rs] = vd;
            }
        }
        __syncthreads();

        ull a00 = 0, a01 = 0, a10 = 0, a11 = 0;   // [dpair][row]
        const ull* hb = hs2 + 2 * rg;
        #pragma unroll 1
        for (int aa = 0; aa < ADAPT; aa += 4) {
            ulonglong2 w0 = *(const ulonglong2*)(Wp + (size_t)(aa + 0) * D_MODEL);
            ulonglong2 w1 = *(const ulonglong2*)(Wp + (size_t)(aa + 1) * D_MODEL);
            ulonglong2 w2 = *(const ulonglong2*)(Wp + (size_t)(aa + 2) * D_MODEL);
            ulonglong2 w3 = *(const ulonglong2*)(Wp + (size_t)(aa + 3) * D_MODEL);
            ulonglong2 h0 = *(const ulonglong2*)(hb + (aa + 0) * RT);
            ulonglong2 h1 = *(const ulonglong2*)(hb + (aa + 1) * RT);
            ulonglong2 h2 = *(const ulonglong2*)(hb + (aa + 2) * RT);
            ulonglong2 h3 = *(const ulonglong2*)(hb + (aa + 3) * RT);
            FMA2(a00, w0.x, h0.x, a00); FMA2(a01, w0.x, h0.y, a01);
            FMA2(a10, w0.y, h0.x, a10); FMA2(a11, w0.y, h0.y, a11);
            FMA2(a00, w1.x, h1.x, a00); FMA2(a01, w1.x, h1.y, a01);
            FMA2(a10, w1.y, h1.x, a10); FMA2(a11, w1.y, h1.y, a11);
            FMA2(a00, w2.x, h2.x, a00); FMA2(a01, w2.x, h2.y, a01);
            FMA2(a10, w2.y, h2.x, a10); FMA2(a11, w2.y, h2.y, a11);
            FMA2(a00, w3.x, h3.x, a00); FMA2(a01, w3.x, h3.y, a01);
            FMA2(a10, w3.y, h3.x, a10); FMA2(a11, w3.y, h3.y, a11);
        }
        ADD2(a00, a00, bb.x); ADD2(a10, a10, bb.y);
        ADD2(a01, a01, bb.x); ADD2(a11, a11, bb.y);
        int r0 = 2 * rg, r1 = 2 * rg + 1;
        if (r0 < n) {
            ulonglong2 s; s.x = a00; s.y = a10;
            *(ulonglong2*)(out + (size_t)g_rows[base + r0] * D_MODEL + d0) = s;
        }
        if (r1 < n) {
            ulonglong2 s; s.x = a01; s.y = a11;
            *(ulonglong2*)(out + (size_t)g_rows[base + r1] * D_MODEL + d0) = s;
        }
    }
}

// ---------------------------------------------------------------------------
extern "C" void kernel_launch(void* const* d_in, const int* in_sizes, int n_in,
                              void* d_out, int out_size) {
    const float* x   = (const float*)d_in[0];
    const int*   src = (const int*)d_in[1];
    const int*   tgt = (const int*)d_in[2];
    const float* W1  = (const float*)d_in[3];
    const float* b1  = (const float*)d_in[4];
    const float* W2  = (const float*)d_in[5];
    const float* b2  = (const float*)d_in[6];
    float* out = (float*)d_out;
    int B = in_sizes[1];  // 1024

    k_build<<<1, 1024>>>(src, tgt, B);
    k_copy<<<128, 256>>>(x, src, tgt, out, B);
    k_gemm1<<<dim3(NPAIR, KC), 256>>>(x, W1);
    k_gemm2<<<dim3(NPAIR, 8), 256>>>(W2, b1, b2, out);
}

// round 7
// speedup vs baseline: 1.1842x; 1.1137x over previous
#include <cuda_runtime.h>

// Problem constants (fixed by dataset)
#define D_MODEL 1024
#define ADAPT   128
#define NUM_LIB 8
#define NPAIR   (NUM_LIB * NUM_LIB)   // 64
#define MAXB    1024
#define KC      4                      // K-split for gemm1
#define KCH     (D_MODEL / KC)         // 256 k per gemm1 CTA
#define RT      16                     // row tile
#define ST1     16                     // k per weight stage (gemm1)
#define NST1    (KCH / ST1)            // 16 stages
#define ST2     16                     // a per weight stage (gemm2)
#define NST2    (ADAPT / ST2)          // 8 stages
#define DC      256                    // d-cols per gemm2 CTA

typedef unsigned long long ull;

// Packed fp32x2 ops (sm_10x)
#define FMA2(d, a, b, c) \
    asm("fma.rn.f32x2 %0, %1, %2, %3;" : "=l"(d) : "l"(a), "l"(b), "l"(c))
#define ADD2(d, a, b) \
    asm("add.rn.f32x2 %0, %1, %2;" : "=l"(d) : "l"(a), "l"(b))
#define PACK2(d, s) \
    asm("mov.b64 %0, {%1, %1};" : "=l"(d) : "f"(s))
// cp.async 16B, L1-bypass (streaming weights)
#define CP16(smem_u32, gptr) \
    asm volatile("cp.async.cg.shared.global [%0], [%1], 16;" \
                 :: "r"(smem_u32), "l"(gptr))
#define CPCOMMIT() asm volatile("cp.async.commit_group;")
#define CPWAIT1()  asm volatile("cp.async.wait_group 1;")
#define CPWAIT0()  asm volatile("cp.async.wait_group 0;")

// Device scratch (no allocations allowed)
__device__ int   g_off[NPAIR + 1];
__device__ int   g_rows[MAXB];
__device__ float g_hp[KC][MAXB * ADAPT];   // partial pre-activation sums (2 MB)

// ---------------------------------------------------------------------------
// Build per-pair CSR of row indices. One CTA, 1024 threads.
// ---------------------------------------------------------------------------
__global__ void k_build(const int* __restrict__ src, const int* __restrict__ tgt, int B) {
    __shared__ int cnt[NPAIR];
    __shared__ int off[NPAIR + 1];
    int t = threadIdx.x;
    if (t < NPAIR) cnt[t] = 0;
    __syncthreads();
    int p = -1, slot = 0;
    if (t < B) {
        int s = src[t], g = tgt[t];
        if (s != g) {
            p = s * NUM_LIB + g;
            slot = atomicAdd(&cnt[p], 1);
        }
    }
    __syncthreads();
    if (t == 0) {
        int acc = 0;
        for (int i = 0; i < NPAIR; i++) { off[i] = acc; acc += cnt[i]; }
        off[NPAIR] = acc;
    }
    __syncthreads();
    if (t <= NPAIR) g_off[t] = off[t];
    if (p >= 0) g_rows[off[p] + slot] = t;
}

// ---------------------------------------------------------------------------
// Identity rows: out[b] = x[b]. 128 CTAs x 256 thr, grid-stride over rows.
// ---------------------------------------------------------------------------
__global__ void __launch_bounds__(256)
k_copy(const float* __restrict__ x,
       const int* __restrict__ src, const int* __restrict__ tgt,
       float* __restrict__ out, int B) {
    for (int b = blockIdx.x; b < B; b += gridDim.x) {
        if (src[b] != tgt[b]) continue;
        const float4* xi = (const float4*)(x + (size_t)b * D_MODEL);
        float4* yo = (float4*)(out + (size_t)b * D_MODEL);
        yo[threadIdx.x] = xi[threadIdx.x];
    }
}

// ---------------------------------------------------------------------------
// GEMM1 (K-split): g_hp[kz][row, a] = x[row, kz*256:+256] . W1[p, slice, a]
// grid (NPAIR, KC), 256 thr. Thread: a-quad aq = t&31 (a0 = aq*4, 2 packed
// pairs via one LDS.128), rg = t>>5 -> row pair {2rg, 2rg+1}.
// Weights cp.async double-buffered gmem->smem; x duplicated f32x2 in smem.
// Inner step: LDS.128(w) + LDS.128(x bcast) + 4x FMA2.
// ---------------------------------------------------------------------------
__global__ void __launch_bounds__(256, 4)
k_gemm1(const float* __restrict__ x, const float* __restrict__ W1) {
    __shared__ __align__(16) ull   xs2[KCH * RT];        // 32 KB [k][r] dup pairs
    __shared__ __align__(16) float ws[2][ST1 * ADAPT];   // 2 x 8 KB
    int p  = blockIdx.x;
    int kz = blockIdx.y;
    int begin = g_off[p], end = g_off[p + 1];
    int t  = threadIdx.x;
    int aq = t & 31;                     // a-quad: a0 = aq*4  (128 a = 32 quads)
    int rg = t >> 5;                     // row pair {2rg, 2rg+1} (8 pairs = 16 rows)
    // staging map (lane-consecutive rows -> conflict-free STS)
    int rs = t & 15;
    int kb = (t >> 4) * 16;
    const float* Wb = W1 + ((size_t)p * D_MODEL + (size_t)kz * KCH) * ADAPT;
    float* hp = g_hp[kz];
    unsigned ws0 = (unsigned)__cvta_generic_to_shared(ws[0]);
    unsigned ws1 = (unsigned)__cvta_generic_to_shared(ws[1]);

    for (int base = begin; base < end; base += RT) {
        int n = min(RT, end - base);
        __syncthreads();                 // previous tile done with xs2/ws
        // prefetch weight stages 0,1 (each: 16k x 128a = 512 float4, 2/thread)
        {
            const float4* g0 = (const float4*)(Wb);
            const float4* g1 = (const float4*)(Wb + ST1 * ADAPT);
            CP16(ws0 + t * 16, g0 + t); CP16(ws0 + (t + 256) * 16, g0 + t + 256);
            CPCOMMIT();
            CP16(ws1 + t * 16, g1 + t); CP16(ws1 + (t + 256) * 16, g1 + t + 256);
            CPCOMMIT();
        }
        // stage x dup pairs: thread -> row rs, k block [kb, kb+16)
        {
            float v[16] = {0,0,0,0,0,0,0,0,0,0,0,0,0,0,0,0};
            if (rs < n) {
                const float4* xr = (const float4*)
                    (x + (size_t)g_rows[base + rs] * D_MODEL + kz * KCH + kb);
                float4 u0 = xr[0], u1 = xr[1], u2 = xr[2], u3 = xr[3];
                v[0]=u0.x; v[1]=u0.y; v[2]=u0.z; v[3]=u0.w;
                v[4]=u1.x; v[5]=u1.y; v[6]=u1.z; v[7]=u1.w;
                v[8]=u2.x; v[9]=u2.y; v[10]=u2.z; v[11]=u2.w;
                v[12]=u3.x; v[13]=u3.y; v[14]=u3.z; v[15]=u3.w;
            }
            #pragma unroll
            for (int i = 0; i < 16; i++) {
                ull vd; PACK2(vd, v[i]);
                xs2[(kb + i) * RT + rs] = vd;
            }
        }

        ull a00 = 0, a01 = 0, a10 = 0, a11 = 0;   // [apair][row]

        #pragma unroll 1
        for (int s = 0; s < NST1; s++) {
            if (s < NST1 - 1) CPWAIT1(); else CPWAIT0();
            __syncthreads();
            const float* wb = ws[s & 1];
            const ull* xb = xs2 + (s * ST1) * RT + 2 * rg;
            #pragma unroll
            for (int kk = 0; kk < ST1; kk++) {
                ulonglong2 w  = *(const ulonglong2*)(wb + kk * ADAPT + aq * 4);
                ulonglong2 xv = *(const ulonglong2*)(xb + kk * RT);
                FMA2(a00, w.x, xv.x, a00); FMA2(a01, w.x, xv.y, a01);
                FMA2(a10, w.y, xv.x, a10); FMA2(a11, w.y, xv.y, a11);
            }
            __syncthreads();             // all readers done before refill
            if (s + 2 < NST1) {
                unsigned wd = (s & 1) ? ws1 : ws0;
                const float4* g = (const float4*)(Wb + (s + 2) * ST1 * ADAPT);
                CP16(wd + t * 16, g + t); CP16(wd + (t + 256) * 16, g + t + 256);
                CPCOMMIT();
            }
        }
        int r0 = 2 * rg, r1 = 2 * rg + 1;
        if (r0 < n) {
            ulonglong2 sv; sv.x = a00; sv.y = a10;
            *(ulonglong2*)(hp + (size_t)g_rows[base + r0] * ADAPT + aq * 4) = sv;
        }
        if (r1 < n) {
            ulonglong2 sv; sv.x = a01; sv.y = a11;
            *(ulonglong2*)(hp + (size_t)g_rows[base + r1] * ADAPT + aq * 4) = sv;
        }
    }
}

// ---------------------------------------------------------------------------
// GEMM2: out[row, d] = relu(sum_kz g_hp + b1) . W2[p,:,d] + b2[p,d]
// grid (NPAIR, 4), 256 thr. Thread: d-pair d0 = dc*256 + (t&127)*2, 8 rows.
// ---------------------------------------------------------------------------
__global__ void __launch_bounds__(256, 4)
k_gemm2(const float* __restrict__ W2, const float* __restrict__ b1,
        const float* __restrict__ b2, float* __restrict__ out) {
    __shared__ __align__(16) ull   hs2[ADAPT * RT];      // 16 KB [a][r] dup pairs
    __shared__ __align__(16) float ws[2][ST2 * DC];      // 2 x 16 KB
    int p  = blockIdx.x;
    int dc = blockIdx.y;
    int begin = g_off[p], end = g_off[p + 1];
    int t    = threadIdx.x;
    int dp   = t & 127;
    int half = t >> 7;
    int rs = t & 15;
    int ab = (t >> 4) * 8;
    const float* Wb = W2 + (size_t)p * ADAPT * D_MODEL + dc * DC;
    ull bb = *(const ull*)(b2 + (size_t)p * D_MODEL + dc * DC + dp * 2);
    unsigned ws0 = (unsigned)__cvta_generic_to_shared(ws[0]);
    unsigned ws1 = (unsigned)__cvta_generic_to_shared(ws[1]);

    for (int base = begin; base < end; base += RT) {
        int n = min(RT, end - base);
        __syncthreads();                 // previous tile done with hs2/ws
        // prefetch weight stages 0,1 (each: 16a x 256d = 1024 float4, 4/thread)
        #pragma unroll
        for (int s = 0; s < 2; s++) {
            unsigned wd = s ? ws1 : ws0;
            #pragma unroll
            for (int j = 0; j < 4; j++) {
                int idx = t + 256 * j;
                int kk = idx >> 6, c = idx & 63;
                CP16(wd + idx * 16,
                     (const float4*)(Wb + (size_t)(s * ST2 + kk) * D_MODEL) + c);
            }
            CPCOMMIT();
        }
        // stage h = relu(sum of K-partials + b1), dup pairs [a][r]
        {
            float v[8] = {0,0,0,0,0,0,0,0};
            if (rs < n) {
                size_t ro = (size_t)g_rows[base + rs] * ADAPT + ab;
                #pragma unroll
                for (int kz = 0; kz < KC; kz++) {
                    const float4* hp4 = (const float4*)(g_hp[kz] + ro);
                    float4 u0 = hp4[0], u1 = hp4[1];
                    v[0]+=u0.x; v[1]+=u0.y; v[2]+=u0.z; v[3]+=u0.w;
                    v[4]+=u1.x; v[5]+=u1.y; v[6]+=u1.z; v[7]+=u1.w;
                }
                const float4* bp = (const float4*)(b1 + p * ADAPT + ab);
                float4 c0 = bp[0], c1 = bp[1];
                v[0]=fmaxf(v[0]+c0.x,0.f); v[1]=fmaxf(v[1]+c0.y,0.f);
                v[2]=fmaxf(v[2]+c0.z,0.f); v[3]=fmaxf(v[3]+c0.w,0.f);
                v[4]=fmaxf(v[4]+c1.x,0.f); v[5]=fmaxf(v[5]+c1.y,0.f);
                v[6]=fmaxf(v[6]+c1.z,0.f); v[7]=fmaxf(v[7]+c1.w,0.f);
            }
            #pragma unroll
            for (int i = 0; i < 8; i++) {
                ull vd; PACK2(vd, v[i]);
                hs2[(ab + i) * RT + rs] = vd;
            }
        }

        ull acc[8];
        #pragma unroll
        for (int j = 0; j < 8; j++) acc[j] = 0;

        #pragma unroll 1
        for (int s = 0; s < NST2; s++) {
            if (s < NST2 - 1) CPWAIT1(); else CPWAIT0();
            __syncthreads();
            const float* wb = ws[s & 1];
            const ull* hb = hs2 + (s * ST2) * RT + half * 8;
            #pragma unroll
            for (int kk = 0; kk < ST2; kk++) {
                ull w = *(const ull*)(wb + kk * DC + dp * 2);
                ulonglong2 h01 = *(const ulonglong2*)(hb + kk * RT);
                ulonglong2 h23 = *(const ulonglong2*)(hb + kk * RT + 2);
                ulonglong2 h45 = *(const ulonglong2*)(hb + kk * RT + 4);
                ulonglong2 h67 = *(const ulonglong2*)(hb + kk * RT + 6);
                FMA2(acc[0], w, h01.x, acc[0]); FMA2(acc[1], w, h01.y, acc[1]);
                FMA2(acc[2], w, h23.x, acc[2]); FMA2(acc[3], w, h23.y, acc[3]);
                FMA2(acc[4], w, h45.x, acc[4]); FMA2(acc[5], w, h45.y, acc[5]);
                FMA2(acc[6], w, h67.x, acc[6]); FMA2(acc[7], w, h67.y, acc[7]);
            }
            __syncthreads();
            if (s + 2 < NST2) {
                unsigned wd = (s & 1) ? ws1 : ws0;
                #pragma unroll
                for (int j = 0; j < 4; j++) {
                    int idx = t + 256 * j;
                    int kk = idx >> 6, c = idx & 63;
                    CP16(wd + idx * 16,
                         (const float4*)(Wb + (size_t)((s + 2) * ST2 + kk) * D_MODEL) + c);
                }
                CPCOMMIT();
            }
        }
        #pragma unroll
        for (int j = 0; j < 8; j++) {
            int r = half * 8 + j;
            if (r < n) {
                ull o; ADD2(o, acc[j], bb);
                *(ull*)(out + (size_t)g_rows[base + r] * D_MODEL + dc * DC + dp * 2) = o;
            }
        }
    }
}

// ---------------------------------------------------------------------------
extern "C" void kernel_launch(void* const* d_in, const int* in_sizes, int n_in,
                              void* d_out, int out_size) {
    const float* x   = (const float*)d_in[0];
    const int*   src = (const int*)d_in[1];
    const int*   tgt = (const int*)d_in[2];
    const float* W1  = (const float*)d_in[3];
    const float* b1  = (const float*)d_in[4];
    const float* W2  = (const float*)d_in[5];
    const float* b2  = (const float*)d_in[6];
    float* out = (float*)d_out;
    int B = in_sizes[1];  // 1024

    k_build<<<1, 1024>>>(src, tgt, B);
    k_copy<<<128, 256>>>(x, src, tgt, out, B);
    k_gemm1<<<dim3(NPAIR, KC), 256>>>(x, W1);
    k_gemm2<<<dim3(NPAIR, 4), 256>>>(W2, b1, b2, out);
}

// round 8
// speedup vs baseline: 1.5730x; 1.3283x over previous
#include <cuda_runtime.h>

// Problem constants (fixed by dataset)
#define D_MODEL 1024
#define ADAPT   128
#define NUM_LIB 8
#define NPAIR   64
#define MAXB    1024
#define KC      8        // k-split for gemm1 (128 k per CTA)
#define KCH     128
#define DC      128      // d-cols per gemm2 CTA
#define NST     16       // pipeline stages per slab (8 rows x 128 cols each)
#define RCAP    32       // row capacity per tile
#define RS      36       // ull stride per k/a line (16B-aligned, bank-spread)

typedef unsigned long long ull;

// Packed fp32x2 ops (sm_10x)
#define FMA2(d,a,b,c) asm("fma.rn.f32x2 %0, %1, %2, %3;":"=l"(d):"l"(a),"l"(b),"l"(c))
#define ADD2(d,a,b)   asm("add.rn.f32x2 %0, %1, %2;":"=l"(d):"l"(a),"l"(b))
#define PACK2(d,s)    asm("mov.b64 %0, {%1, %1};":"=l"(d):"f"(s))
// cp.async 16B, L1-bypass
#define CP16(dst,src) asm volatile("cp.async.cg.shared.global [%0], [%1], 16;"::"r"(dst),"l"(src))
#define CPCOMMIT()    asm volatile("cp.async.commit_group;")
#define CPWAIT2()     asm volatile("cp.async.wait_group 2;")

// Device scratch (no allocations allowed)
__device__ int   g_cnt[NPAIR];
__device__ int   g_rows[NPAIR][MAXB];          // atomic buckets (256 KB)
__device__ float g_hp[KC][MAXB * ADAPT];       // partial pre-activations (4 MB)

// ---------------------------------------------------------------------------
// Bucket rows by pair via global atomics (no scan). One CTA, 1024 threads.
// ---------------------------------------------------------------------------
__global__ void k_build(const int* __restrict__ src, const int* __restrict__ tgt, int B) {
    int t = threadIdx.x;
    if (t < NPAIR) g_cnt[t] = 0;
    __syncthreads();
    if (t < B) {
        int s = src[t], g = tgt[t];
        if (s != g) {
            int p = s * NUM_LIB + g;
            int slot = atomicAdd(&g_cnt[p], 1);
            g_rows[p][slot] = t;
        }
    }
}

// ---------------------------------------------------------------------------
// Identity rows: out[b] = x[b]
// ---------------------------------------------------------------------------
__global__ void __launch_bounds__(256)
k_copy(const float* __restrict__ x,
       const int* __restrict__ src, const int* __restrict__ tgt,
       float* __restrict__ out, int B) {
    for (int b = blockIdx.x; b < B; b += gridDim.x) {
        if (src[b] != tgt[b]) continue;
        const float4* xi = (const float4*)(x + (size_t)b * D_MODEL);
        float4* yo = (float4*)(out + (size_t)b * D_MODEL);
        yo[threadIdx.x] = xi[threadIdx.x];
    }
}

// ---------------------------------------------------------------------------
// GEMM1 (k-split): g_hp[kz][row, a] = x[row, kz*128:+128] . W1[p, slice, a]
// grid (64, 8), 256 thr, dyn smem: xs2 (128 k x 36 ull) + ws ring (4 x 4 KB).
// Warp = 4 rows; thread also owns a-quad tq*4. Depth-4 cp.async weight ring.
// ---------------------------------------------------------------------------
__global__ void __launch_bounds__(256, 4)
k_gemm1(const float* __restrict__ x, const float* __restrict__ W1) {
    extern __shared__ __align__(16) char smx[];
    ull*   xs2 = (ull*)smx;                     // [k][RS] duplicated pairs
    float* ws  = (float*)(smx + KCH * RS * 8);  // [4][8*128]
    int p  = blockIdx.x;
    int kz = blockIdx.y;
    int n = g_cnt[p];
    if (n == 0) return;
    int t  = threadIdx.x;
    int tq = t & 31;                 // a-quad (a0 = tq*4)
    int rg = t >> 5;                 // row group = warp (rows rg*4..+3)
    int rs = t >> 3;                 // staging row (0..31)
    int a8 = (t & 7) * 4;            // staging k base
    const int* rows = g_rows[p];
    const float* Wb = W1 + ((size_t)p * D_MODEL + (size_t)kz * KCH) * ADAPT;
    float* hp = g_hp[kz];
    unsigned wsb = (unsigned)__cvta_generic_to_shared(ws);
    int wkr = t >> 5;                // stage line (0..7)
    int wav = (t & 31) * 4;          // stage col (float4)

    for (int base = 0; base < n; base += RCAP) {
        int nn = min(RCAP, n - base);
        __syncthreads();             // previous tile fully consumed
        // prologue: weight stages 0..2
        #pragma unroll
        for (int s = 0; s < 3; s++) {
            CP16(wsb + s * 4096u + (unsigned)(wkr * ADAPT + wav) * 4u,
                 Wb + (size_t)(s * 8 + wkr) * ADAPT + wav);
            CPCOMMIT();
        }
        // stage x duplicated pairs, transposed [k][row]
        {
            const float* xr = (rs < nn)
                ? x + (size_t)rows[base + rs] * D_MODEL + kz * KCH : 0;
            #pragma unroll
            for (int c = 0; c < 4; c++) {
                float4 u = make_float4(0.f, 0.f, 0.f, 0.f);
                if (rs < nn) u = *(const float4*)(xr + a8 + c * 32);
                ull q0, q1, q2, q3;
                PACK2(q0, u.x); PACK2(q1, u.y); PACK2(q2, u.z); PACK2(q3, u.w);
                int k = a8 + c * 32;
                xs2[(k + 0) * RS + rs] = q0; xs2[(k + 1) * RS + rs] = q1;
                xs2[(k + 2) * RS + rs] = q2; xs2[(k + 3) * RS + rs] = q3;
            }
        }
        ull acc[8];
        #pragma unroll
        for (int j = 0; j < 8; j++) acc[j] = 0;
        bool active = (rg * 4 < nn);

        #pragma unroll 1
        for (int s = 0; s < NST; s++) {
            CPWAIT2();
            __syncthreads();         // stage s arrived; slot (s+3)&3 free
            if (s + 3 < NST)
                CP16(wsb + ((s + 3) & 3) * 4096u + (unsigned)(wkr * ADAPT + wav) * 4u,
                     Wb + (size_t)((s + 3) * 8 + wkr) * ADAPT + wav);
            CPCOMMIT();              // unconditional: uniform group indexing
            if (active) {
                const float* wl = ws + (s & 3) * (8 * ADAPT);
                const ull* xb = xs2 + rg * 4;
                #pragma unroll
                for (int kk = 0; kk < 8; kk++) {
                    ulonglong2 w   = *(const ulonglong2*)(wl + kk * ADAPT + tq * 4);
                    ulonglong2 x01 = *(const ulonglong2*)(xb + (s * 8 + kk) * RS);
                    ulonglong2 x23 = *(const ulonglong2*)(xb + (s * 8 + kk) * RS + 2);
                    FMA2(acc[0], w.x, x01.x, acc[0]); FMA2(acc[1], w.y, x01.x, acc[1]);
                    FMA2(acc[2], w.x, x01.y, acc[2]); FMA2(acc[3], w.y, x01.y, acc[3]);
                    FMA2(acc[4], w.x, x23.x, acc[4]); FMA2(acc[5], w.y, x23.x, acc[5]);
                    FMA2(acc[6], w.x, x23.y, acc[6]); FMA2(acc[7], w.y, x23.y, acc[7]);
                }
            }
        }
        #pragma unroll
        for (int j = 0; j < 4; j++) {
            int r = rg * 4 + j;
            if (r < nn) {
                ulonglong2 sv; sv.x = acc[j * 2]; sv.y = acc[j * 2 + 1];
                *(ulonglong2*)(hp + (size_t)rows[base + r] * ADAPT + tq * 4) = sv;
            }
        }
    }
}

// ---------------------------------------------------------------------------
// GEMM2: out[row, d] = relu(sum_kz g_hp + b1) . W2[p,:,d] + b2[p,d]
// grid (64, 8), 256 thr, dyn smem: hs2 (128 a x 36 ull) + ws ring (4 x 4 KB).
// ---------------------------------------------------------------------------
__global__ void __launch_bounds__(256, 4)
k_gemm2(const float* __restrict__ W2, const float* __restrict__ b1,
        const float* __restrict__ b2, float* __restrict__ out) {
    extern __shared__ __align__(16) char smx[];
    ull*   hs2 = (ull*)smx;                      // [a][RS] duplicated pairs
    float* ws  = (float*)(smx + ADAPT * RS * 8); // [4][8*128]
    int p  = blockIdx.x;
    int dc = blockIdx.y;
    int n = g_cnt[p];
    if (n == 0) return;
    int t  = threadIdx.x;
    int tq = t & 31;
    int rg = t >> 5;
    int rs = t >> 3;
    int a8 = (t & 7) * 4;
    const int* rows = g_rows[p];
    const float* Wb = W2 + (size_t)p * ADAPT * D_MODEL + dc * DC;
    unsigned wsb = (unsigned)__cvta_generic_to_shared(ws);
    int war = t >> 5;
    int wdv = (t & 31) * 4;
    int d0 = dc * DC + tq * 4;
    ulonglong2 bb = *(const ulonglong2*)(b2 + (size_t)p * D_MODEL + d0);

    for (int base = 0; base < n; base += RCAP) {
        int nn = min(RCAP, n - base);
        __syncthreads();
        #pragma unroll
        for (int s = 0; s < 3; s++) {
            CP16(wsb + s * 4096u + (unsigned)(war * DC + wdv) * 4u,
                 Wb + (size_t)(s * 8 + war) * D_MODEL + wdv);
            CPCOMMIT();
        }
        // stage h = relu(sum of K-partials + b1), duplicated pairs [a][row]
        {
            size_t ro = (rs < nn) ? (size_t)rows[base + rs] * ADAPT : 0;
            #pragma unroll
            for (int c = 0; c < 4; c++) {
                int a = a8 + c * 32;
                float4 v = make_float4(0.f, 0.f, 0.f, 0.f);
                if (rs < nn) {
                    #pragma unroll
                    for (int kzi = 0; kzi < KC; kzi++) {
                        float4 u = *(const float4*)(g_hp[kzi] + ro + a);
                        v.x += u.x; v.y += u.y; v.z += u.z; v.w += u.w;
                    }
                    float4 b = *(const float4*)(b1 + p * ADAPT + a);
                    v.x = fmaxf(v.x + b.x, 0.f); v.y = fmaxf(v.y + b.y, 0.f);
                    v.z = fmaxf(v.z + b.z, 0.f); v.w = fmaxf(v.w + b.w, 0.f);
                }
                ull q0, q1, q2, q3;
                PACK2(q0, v.x); PACK2(q1, v.y); PACK2(q2, v.z); PACK2(q3, v.w);
                hs2[(a + 0) * RS + rs] = q0; hs2[(a + 1) * RS + rs] = q1;
                hs2[(a + 2) * RS + rs] = q2; hs2[(a + 3) * RS + rs] = q3;
            }
        }
        ull acc[8];
        #pragma unroll
        for (int j = 0; j < 8; j++) acc[j] = 0;
        bool active = (rg * 4 < nn);

        #pragma unroll 1
        for (int s = 0; s < NST; s++) {
            CPWAIT2();
            __syncthreads();
            if (s + 3 < NST)
                CP16(wsb + ((s + 3) & 3) * 4096u + (unsigned)(war * DC + wdv) * 4u,
                     Wb + (size_t)((s + 3) * 8 + war) * D_MODEL + wdv);
            CPCOMMIT();
            if (active) {
                const float* wl = ws + (s & 3) * (8 * DC);
                const ull* hb = hs2 + rg * 4;
                #pragma unroll
                for (int kk = 0; kk < 8; kk++) {
                    ulonglong2 w   = *(const ulonglong2*)(wl + kk * DC + tq * 4);
                    ulonglong2 h01 = *(const ulonglong2*)(hb + (s * 8 + kk) * RS);
                    ulonglong2 h23 = *(const ulonglong2*)(hb + (s * 8 + kk) * RS + 2);
                    FMA2(acc[0], w.x, h01.x, acc[0]); FMA2(acc[1], w.y, h01.x, acc[1]);
                    FMA2(acc[2], w.x, h01.y, acc[2]); FMA2(acc[3], w.y, h01.y, acc[3]);
                    FMA2(acc[4], w.x, h23.x, acc[4]); FMA2(acc[5], w.y, h23.x, acc[5]);
                    FMA2(acc[6], w.x, h23.y, acc[6]); FMA2(acc[7], w.y, h23.y, acc[7]);
                }
            }
        }
        #pragma unroll
        for (int j = 0; j < 4; j++) {
            int r = rg * 4 + j;
            if (r < nn) {
                ulonglong2 sv;
                ADD2(sv.x, acc[j * 2], bb.x);
                ADD2(sv.y, acc[j * 2 + 1], bb.y);
                *(ulonglong2*)(out + (size_t)rows[base + r] * D_MODEL + d0) = sv;
            }
        }
    }
}

// ---------------------------------------------------------------------------
#define SMEM1 (KCH * RS * 8 + 4 * 8 * ADAPT * 4)    // 36864 + 16384 = 53248
#define SMEM2 (ADAPT * RS * 8 + 4 * 8 * DC * 4)     // 53248

extern "C" void kernel_launch(void* const* d_in, const int* in_sizes, int n_in,
                              void* d_out, int out_size) {
    const float* x   = (const float*)d_in[0];
    const int*   src = (const int*)d_in[1];
    const int*   tgt = (const int*)d_in[2];
    const float* W1  = (const float*)d_in[3];
    const float* b1  = (const float*)d_in[4];
    const float* W2  = (const float*)d_in[5];
    const float* b2  = (const float*)d_in[6];
    float* out = (float*)d_out;
    int B = in_sizes[1];  // 1024

    cudaFuncSetAttribute(k_gemm1, cudaFuncAttributeMaxDynamicSharedMemorySize, SMEM1);
    cudaFuncSetAttribute(k_gemm2, cudaFuncAttributeMaxDynamicSharedMemorySize, SMEM2);

    k_build<<<1, 1024>>>(src, tgt, B);
    k_copy<<<128, 256>>>(x, src, tgt, out, B);
    k_gemm1<<<dim3(NPAIR, KC), 256, SMEM1>>>(x, W1);
    k_gemm2<<<dim3(NPAIR, 8), 256, SMEM2>>>(W2, b1, b2, out);
}

// round 9
// speedup vs baseline: 1.6237x; 1.0322x over previous
#include <cuda_runtime.h>

// Problem constants (fixed by dataset)
#define D_MODEL 1024
#define ADAPT   128
#define NUM_LIB 8
#define NPAIR   64
#define MAXB    1024
#define KC      8        // k-split for gemm1 (128 k per CTA)
#define KCH     128
#define DC      128      // d-cols per gemm2 CTA
#define NST     16       // stages per slab (8 lines x 128 cols = 4 KB each)
#define RT      16       // row capacity per tile
#define RS      20       // ull stride per k/a line (2-way-conflict staging, 16B aligned)
#define RING    6        // cp.async ring depth

typedef unsigned long long ull;

// Packed fp32x2 ops (sm_10x)
#define FMA2(d,a,b,c) asm("fma.rn.f32x2 %0, %1, %2, %3;":"=l"(d):"l"(a),"l"(b),"l"(c))
#define ADD2(d,a,b)   asm("add.rn.f32x2 %0, %1, %2;":"=l"(d):"l"(a),"l"(b))
#define PACK2(d,s)    asm("mov.b64 %0, {%1, %1};":"=l"(d):"f"(s))
// cp.async 16B, L1-bypass
#define CP16(dst,src) asm volatile("cp.async.cg.shared.global [%0], [%1], 16;"::"r"(dst),"l"(src))
#define CPCOMMIT()    asm volatile("cp.async.commit_group;")
#define CPWAIT4()     asm volatile("cp.async.wait_group 4;")

// Device scratch (no allocations allowed)
__device__ int   g_cnt[NPAIR];
__device__ int   g_rows[NPAIR][MAXB];
__device__ float g_hp[KC][MAXB * ADAPT];   // K-split partial pre-activations (4 MB)
__device__ float g_h[MAXB * ADAPT];        // relu(sum + b1) (512 KB)

// ---------------------------------------------------------------------------
// Bucket rows by pair via global atomics. One CTA, 1024 threads.
// ---------------------------------------------------------------------------
__global__ void k_build(const int* __restrict__ src, const int* __restrict__ tgt, int B) {
    int t = threadIdx.x;
    if (t < NPAIR) g_cnt[t] = 0;
    __syncthreads();
    if (t < B) {
        int s = src[t], g = tgt[t];
        if (s != g) {
            int p = s * NUM_LIB + g;
            int slot = atomicAdd(&g_cnt[p], 1);
            g_rows[p][slot] = t;
        }
    }
}

// ---------------------------------------------------------------------------
// Identity rows: out[b] = x[b]
// ---------------------------------------------------------------------------
__global__ void __launch_bounds__(256)
k_copy(const float* __restrict__ x,
       const int* __restrict__ src, const int* __restrict__ tgt,
       float* __restrict__ out, int B) {
    for (int b = blockIdx.x; b < B; b += gridDim.x) {
        if (src[b] != tgt[b]) continue;
        const float4* xi = (const float4*)(x + (size_t)b * D_MODEL);
        float4* yo = (float4*)(out + (size_t)b * D_MODEL);
        yo[threadIdx.x] = xi[threadIdx.x];
    }
}

// ---------------------------------------------------------------------------
// k_act: g_h = relu(sum_kz g_hp + b1). One float4 per thread, 128 CTAs x 256.
// ---------------------------------------------------------------------------
__global__ void __launch_bounds__(256)
k_act(const int* __restrict__ src, const int* __restrict__ tgt,
      const float* __restrict__ b1) {
    int idx = blockIdx.x * 256 + threadIdx.x;       // (row, quad)
    int row = idx >> 5;
    int q   = idx & 31;
    int s = src[row], g = tgt[row];
    if (s == g) return;
    int p = s * NUM_LIB + g;
    size_t off = (size_t)row * ADAPT + q * 4;
    float4 v = make_float4(0.f, 0.f, 0.f, 0.f);
    #pragma unroll
    for (int kz = 0; kz < KC; kz++) {
        float4 u = *(const float4*)(g_hp[kz] + off);
        v.x += u.x; v.y += u.y; v.z += u.z; v.w += u.w;
    }
    float4 b = *(const float4*)(b1 + p * ADAPT + q * 4);
    v.x = fmaxf(v.x + b.x, 0.f); v.y = fmaxf(v.y + b.y, 0.f);
    v.z = fmaxf(v.z + b.z, 0.f); v.w = fmaxf(v.w + b.w, 0.f);
    *(float4*)(g_h + off) = v;
}

// ---------------------------------------------------------------------------
// GEMM1 (k-split): g_hp[kz][row, a] = x[row, kz*128:+128] . W1[p, slice, a]
// grid (64, 8), 128 thr. Thread: a-quad tq = t&31, warp rg = t>>5 -> 4 rows.
// Depth-6 cp.async weight ring (wait_group 4); x duplicated f32x2 in smem.
// ---------------------------------------------------------------------------
__global__ void __launch_bounds__(128, 5)
k_gemm1(const float* __restrict__ x, const float* __restrict__ W1) {
    extern __shared__ __align__(16) char smx[];
    ull*   xs2 = (ull*)smx;                       // [128 k][RS] dup pairs (20 KB)
    float* ws  = (float*)(smx + KCH * RS * 8);    // ring [6][8*128] (24 KB)
    int p  = blockIdx.x;
    int kz = blockIdx.y;
    int n = g_cnt[p];
    if (n == 0) return;
    int t  = threadIdx.x;
    int tq = t & 31;                  // a-quad
    int rg = t >> 5;                  // warp -> rows rg*4..+3
    int js = t & 7;                   // staging k residue (stride-8 ownership)
    int rs = t >> 3;                  // staging row 0..15
    const int* rows = g_rows[p];
    const float* Wb = W1 + ((size_t)p * D_MODEL + (size_t)kz * KCH) * ADAPT;
    float* hp = g_hp[kz];
    unsigned wsb = (unsigned)__cvta_generic_to_shared(ws);

    for (int base = 0; base < n; base += RT) {
        int nn = min(RT, n - base);
        __syncthreads();              // previous tile fully consumed
        // prologue: weight stages 0..4 (each 4 KB = 256 float4, 2 per thread)
        #pragma unroll
        for (int s = 0; s < RING - 1; s++) {
            CP16(wsb + s * 4096u + (unsigned)t * 16u,
                 (const float4*)(Wb + (size_t)s * 8 * ADAPT) + t);
            CP16(wsb + s * 4096u + (unsigned)(t + 128) * 16u,
                 (const float4*)(Wb + (size_t)s * 8 * ADAPT) + t + 128);
            CPCOMMIT();
        }
        // stage x duplicated pairs [k][row]; k = js + 8c (2-way STS conflicts)
        {
            const float* xr = (rs < nn)
                ? x + (size_t)rows[base + rs] * D_MODEL + kz * KCH : 0;
            #pragma unroll
            for (int c = 0; c < 16; c++) {
                int k = js + 8 * c;
                float v = (rs < nn) ? xr[k] : 0.f;
                ull vd; PACK2(vd, v);
                xs2[k * RS + rs] = vd;
            }
        }
        ull acc[8];
        #pragma unroll
        for (int j = 0; j < 8; j++) acc[j] = 0;
        bool active = (rg * 4 < nn);
        int cons = 0, prod = RING - 1;

        #pragma unroll 1
        for (int s = 0; s < NST; s++) {
            CPWAIT4();
            __syncthreads();          // stage s arrived for all threads
            if (s + RING - 1 < NST) { // refill slot prod with stage s+5
                const float4* g = (const float4*)(Wb + (size_t)(s + RING - 1) * 8 * ADAPT);
                CP16(wsb + prod * 4096u + (unsigned)t * 16u, g + t);
                CP16(wsb + prod * 4096u + (unsigned)(t + 128) * 16u, g + t + 128);
            }
            CPCOMMIT();               // unconditional: uniform group indexing
            if (active) {
                const float* wl = ws + cons * (8 * ADAPT);
                const ull* xb = xs2 + (s * 8) * RS + rg * 4;
                #pragma unroll
                for (int kk = 0; kk < 8; kk++) {
                    ulonglong2 w   = *(const ulonglong2*)(wl + kk * ADAPT + tq * 4);
                    ulonglong2 x01 = *(const ulonglong2*)(xb + kk * RS);
                    ulonglong2 x23 = *(const ulonglong2*)(xb + kk * RS + 2);
                    FMA2(acc[0], w.x, x01.x, acc[0]); FMA2(acc[1], w.y, x01.x, acc[1]);
                    FMA2(acc[2], w.x, x01.y, acc[2]); FMA2(acc[3], w.y, x01.y, acc[3]);
                    FMA2(acc[4], w.x, x23.x, acc[4]); FMA2(acc[5], w.y, x23.x, acc[5]);
                    FMA2(acc[6], w.x, x23.y, acc[6]); FMA2(acc[7], w.y, x23.y, acc[7]);
                }
            }
            if (++cons == RING) cons = 0;
            if (++prod == RING) prod = 0;
        }
        #pragma unroll
        for (int j = 0; j < 4; j++) {
            int r = rg * 4 + j;
            if (r < nn) {
                ulonglong2 sv; sv.x = acc[j * 2]; sv.y = acc[j * 2 + 1];
                *(ulonglong2*)(hp + (size_t)rows[base + r] * ADAPT + tq * 4) = sv;
            }
        }
    }
}

// ---------------------------------------------------------------------------
// GEMM2: out[row, d] = g_h[row,:] . W2[p,:,d] + b2[p,d]
// grid (64, 8), 128 thr. Thread: d-quad tq, warp rg -> 4 rows. Same pipeline.
// ---------------------------------------------------------------------------
__global__ void __launch_bounds__(128, 5)
k_gemm2(const float* __restrict__ W2, const float* __restrict__ b2,
        float* __restrict__ out) {
    extern __shared__ __align__(16) char smx[];
    ull*   hs2 = (ull*)smx;                       // [128 a][RS] dup pairs (20 KB)
    float* ws  = (float*)(smx + ADAPT * RS * 8);  // ring [6][8*128] (24 KB)
    int p  = blockIdx.x;
    int dc = blockIdx.y;
    int n = g_cnt[p];
    if (n == 0) return;
    int t  = threadIdx.x;
    int tq = t & 31;
    int rg = t >> 5;
    int js = t & 7;
    int rs = t >> 3;
    const int* rows = g_rows[p];
    const float* Wb = W2 + (size_t)p * ADAPT * D_MODEL + dc * DC;
    int d0 = dc * DC + tq * 4;
    ulonglong2 bb = *(const ulonglong2*)(b2 + (size_t)p * D_MODEL + d0);
    unsigned wsb = (unsigned)__cvta_generic_to_shared(ws);
    int wline = t >> 5;               // refill: 4 lines per shot (t covers 128 f4)
    int wcol  = (t & 31);

    for (int base = 0; base < n; base += RT) {
        int nn = min(RT, n - base);
        __syncthreads();
        // prologue: stages 0..4; stage = 8 a-lines x 128 d = 256 float4
        #pragma unroll
        for (int s = 0; s < RING - 1; s++) {
            CP16(wsb + s * 4096u + (unsigned)(wline * 32 + wcol) * 16u,
                 (const float4*)(Wb + (size_t)(s * 8 + wline) * D_MODEL) + wcol);
            CP16(wsb + s * 4096u + (unsigned)((wline + 4) * 32 + wcol) * 16u,
                 (const float4*)(Wb + (size_t)(s * 8 + wline + 4) * D_MODEL) + wcol);
            CPCOMMIT();
        }
        // stage h duplicated pairs [a][row]; a = js + 8c
        {
            const float* hr = (rs < nn) ? g_h + (size_t)rows[base + rs] * ADAPT : 0;
            #pragma unroll
            for (int c = 0; c < 16; c++) {
                int a = js + 8 * c;
                float v = (rs < nn) ? hr[a] : 0.f;
                ull vd; PACK2(vd, v);
                hs2[a * RS + rs] = vd;
            }
        }
        ull acc[8];
        #pragma unroll
        for (int j = 0; j < 8; j++) acc[j] = 0;
        bool active = (rg * 4 < nn);
        int cons = 0, prod = RING - 1;

        #pragma unroll 1
        for (int s = 0; s < NST; s++) {
            CPWAIT4();
            __syncthreads();
            if (s + RING - 1 < NST) {
                int sl = (s + RING - 1) * 8;
                CP16(wsb + prod * 4096u + (unsigned)(wline * 32 + wcol) * 16u,
                     (const float4*)(Wb + (size_t)(sl + wline) * D_MODEL) + wcol);
                CP16(wsb + prod * 4096u + (unsigned)((wline + 4) * 32 + wcol) * 16u,
                     (const float4*)(Wb + (size_t)(sl + wline + 4) * D_MODEL) + wcol);
            }
            CPCOMMIT();
            if (active) {
                const float* wl = ws + cons * (8 * DC);
                const ull* hb = hs2 + (s * 8) * RS + rg * 4;
                #pragma unroll
                for (int kk = 0; kk < 8; kk++) {
                    ulonglong2 w   = *(const ulonglong2*)(wl + kk * DC + tq * 4);
                    ulonglong2 h01 = *(const ulonglong2*)(hb + kk * RS);
                    ulonglong2 h23 = *(const ulonglong2*)(hb + kk * RS + 2);
                    FMA2(acc[0], w.x, h01.x, acc[0]); FMA2(acc[1], w.y, h01.x, acc[1]);
                    FMA2(acc[2], w.x, h01.y, acc[2]); FMA2(acc[3], w.y, h01.y, acc[3]);
                    FMA2(acc[4], w.x, h23.x, acc[4]); FMA2(acc[5], w.y, h23.x, acc[5]);
                    FMA2(acc[6], w.x, h23.y, acc[6]); FMA2(acc[7], w.y, h23.y, acc[7]);
                }
            }
            if (++cons == RING) cons = 0;
            if (++prod == RING) prod = 0;
        }
        #pragma unroll
        for (int j = 0; j < 4; j++) {
            int r = rg * 4 + j;
            if (r < nn) {
                ulonglong2 sv;
                ADD2(sv.x, acc[j * 2], bb.x);
                ADD2(sv.y, acc[j * 2 + 1], bb.y);
                *(ulonglong2*)(out + (size_t)rows[base + r] * D_MODEL + d0) = sv;
            }
        }
    }
}

// ---------------------------------------------------------------------------
#define SMEM1 (KCH * RS * 8 + RING * 8 * ADAPT * 4)   // 20480 + 24576 = 45056
#define SMEM2 (ADAPT * RS * 8 + RING * 8 * DC * 4)    // 45056

extern "C" void kernel_launch(void* const* d_in, const int* in_sizes, int n_in,
                              void* d_out, int out_size) {
    const float* x   = (const float*)d_in[0];
    const int*   src = (const int*)d_in[1];
    const int*   tgt = (const int*)d_in[2];
    const float* W1  = (const float*)d_in[3];
    const float* b1  = (const float*)d_in[4];
    const float* W2  = (const float*)d_in[5];
    const float* b2  = (const float*)d_in[6];
    float* out = (float*)d_out;
    int B = in_sizes[1];  // 1024

    cudaFuncSetAttribute(k_gemm1, cudaFuncAttributeMaxDynamicSharedMemorySize, SMEM1);
    cudaFuncSetAttribute(k_gemm2, cudaFuncAttributeMaxDynamicSharedMemorySize, SMEM2);

    k_build<<<1, 1024>>>(src, tgt, B);
    k_copy<<<128, 256>>>(x, src, tgt, out, B);
    k_gemm1<<<dim3(NPAIR, KC), 128, SMEM1>>>(x, W1);
    k_act<<<MAXB * ADAPT / 4 / 256, 256>>>(src, tgt, b1);
    k_gemm2<<<dim3(NPAIR, 8), 128, SMEM2>>>(W2, b2, out);
}

// round 11
// speedup vs baseline: 1.9444x; 1.1975x over previous
#include <cuda_runtime.h>

// Problem constants (fixed by dataset)
#define D_MODEL 1024
#define ADAPT   128
#define NUM_LIB 8
#define NPAIR   64
#define MAXB    1024
#define KC      8        // k-split for gemm1 (128 k per CTA)
#define KCH     128
#define DC      128      // d-cols per gemm2 CTA
#define NST     16       // stages per slab (8 lines x 128 cols = 4 KB each)
#define RT      32       // row capacity per tile (covers whole pair)
#define RSF     36       // float stride per k/a line (aligned, 2-way STS)
#define RING    6        // cp.async ring depth

typedef unsigned long long ull;

// Packed fp32x2 ops (sm_10x)
#define FMA2(d,a,b,c) asm("fma.rn.f32x2 %0, %1, %2, %3;":"=l"(d):"l"(a),"l"(b),"l"(c))
#define PACK2(d,s)    asm("mov.b64 %0, {%1, %1};":"=l"(d):"f"(s))
#define UNPK2(lo,hi,s) asm("mov.b64 {%0, %1}, %2;":"=f"(lo),"=f"(hi):"l"(s))
// cp.async 16B, L1-bypass
#define CP16(dst,src) asm volatile("cp.async.cg.shared.global [%0], [%1], 16;"::"r"(dst),"l"(src))
#define CPCOMMIT()    asm volatile("cp.async.commit_group;")
#define CPWAIT4()     asm volatile("cp.async.wait_group 4;")

// Device scratch (no allocations allowed)
__device__ int   g_cnt[NPAIR];
__device__ int   g_rows[NPAIR][MAXB];
__device__ float g_hp[KC][MAXB * ADAPT];   // K-split partial pre-activations
__device__ float g_h[MAXB * ADAPT];        // relu(sum + b1)

// ---------------------------------------------------------------------------
__global__ void k_build(const int* __restrict__ src, const int* __restrict__ tgt, int B) {
    int t = threadIdx.x;
    if (t < NPAIR) g_cnt[t] = 0;
    __syncthreads();
    if (t < B) {
        int s = src[t], g = tgt[t];
        if (s != g) {
            int p = s * NUM_LIB + g;
            int slot = atomicAdd(&g_cnt[p], 1);
            g_rows[p][slot] = t;
        }
    }
}

// ---------------------------------------------------------------------------
__global__ void __launch_bounds__(256)
k_copy(const float* __restrict__ x,
       const int* __restrict__ src, const int* __restrict__ tgt,
       float* __restrict__ out, int B) {
    for (int b = blockIdx.x; b < B; b += gridDim.x) {
        if (src[b] != tgt[b]) continue;
        const float4* xi = (const float4*)(x + (size_t)b * D_MODEL);
        float4* yo = (float4*)(out + (size_t)b * D_MODEL);
        yo[threadIdx.x] = xi[threadIdx.x];
    }
}

// ---------------------------------------------------------------------------
// k_act: g_h = relu(sum_kz g_hp + b1). 256 CTAs x 256 thr, one float2 each.
// ---------------------------------------------------------------------------
__global__ void __launch_bounds__(256)
k_act(const int* __restrict__ src, const int* __restrict__ tgt,
      const float* __restrict__ b1) {
    int idx = blockIdx.x * 256 + threadIdx.x;   // over 65536 float2
    int row = idx >> 6;
    int q   = idx & 63;
    int s = src[row], g = tgt[row];
    if (s == g) return;
    int p = s * NUM_LIB + g;
    size_t off = (size_t)row * ADAPT + q * 2;
    float2 v = make_float2(0.f, 0.f);
    #pragma unroll
    for (int kz = 0; kz < KC; kz++) {
        float2 u = *(const float2*)(g_hp[kz] + off);
        v.x += u.x; v.y += u.y;
    }
    float2 b = *(const float2*)(b1 + p * ADAPT + q * 2);
    v.x = fmaxf(v.x + b.x, 0.f);
    v.y = fmaxf(v.y + b.y, 0.f);
    *(float2*)(g_h + off) = v;
}

// ---------------------------------------------------------------------------
// GEMM1 (k-split): g_hp[kz][row, a] = x[row, kz*128:+128] . W1[p, slice, a]
// grid (64, 8), 128 thr. Thread: a-quad tq = t&31, warp rg = t>>5 -> 8 rows.
// acc packs ROW pairs; weights lane-duplicated via PACK2 (alu pipe).
// Depth-6 cp.async weight ring; x staged as plain floats [k][row].
// ---------------------------------------------------------------------------
__global__ void __launch_bounds__(128, 5)
k_gemm1(const float* __restrict__ x, const float* __restrict__ W1) {
    extern __shared__ __align__(16) char smx[];
    float* xs = (float*)smx;                      // [128 k][RSF] (18 KB)
    float* ws = (float*)(smx + KCH * RSF * 4);    // ring [6][8*128] (24 KB)
    int p  = blockIdx.x;
    int kz = blockIdx.y;
    int n = g_cnt[p];
    if (n == 0) return;
    int t  = threadIdx.x;
    int tq = t & 31;                  // a-quad (a0 = tq*4)
    int rg = t >> 5;                  // warp -> rows rg*8..+7
    int js = t & 3;                   // staging k residue
    int rs = t >> 2;                  // staging row 0..31
    const int* rows = g_rows[p];
    const float* Wb = W1 + ((size_t)p * D_MODEL + (size_t)kz * KCH) * ADAPT;
    float* hp = g_hp[kz];
    unsigned wsb = (unsigned)__cvta_generic_to_shared(ws);

    for (int base = 0; base < n; base += RT) {
        int nn = min(RT, n - base);
        __syncthreads();              // previous tile fully consumed
        // prologue: weight stages 0..4 (each 4 KB = 256 float4, 2 per thread)
        #pragma unroll
        for (int s = 0; s < RING - 1; s++) {
            const float4* g = (const float4*)(Wb + (size_t)s * 8 * ADAPT);
            CP16(wsb + s * 4096u + (unsigned)t * 16u, g + t);
            CP16(wsb + s * 4096u + (unsigned)(t + 128) * 16u, g + t + 128);
            CPCOMMIT();
        }
        // stage x plain floats [k][row]; thread: row rs, k = js + 4c
        {
            const float* xr = (rs < nn)
                ? x + (size_t)rows[base + rs] * D_MODEL + kz * KCH : 0;
            #pragma unroll
            for (int c = 0; c < 32; c++) {
                int k = js + 4 * c;
                xs[k * RSF + rs] = (rs < nn) ? xr[k] : 0.f;
            }
        }
        ull acc[16];                  // [a 0..3][row-pair 0..3]
        #pragma unroll
        for (int j = 0; j < 16; j++) acc[j] = 0;
        bool active = (rg * 8 < nn);
        int cons = 0, prod = RING - 1;

        #pragma unroll 1
        for (int s = 0; s < NST; s++) {
            CPWAIT4();
            __syncthreads();
            if (s + RING - 1 < NST) {
                const float4* g = (const float4*)(Wb + (size_t)(s + RING - 1) * 8 * ADAPT);
                CP16(wsb + prod * 4096u + (unsigned)t * 16u, g + t);
                CP16(wsb + prod * 4096u + (unsigned)(t + 128) * 16u, g + t + 128);
            }
            CPCOMMIT();               // unconditional: uniform group indexing
            if (active) {
                const float* wl = ws + cons * (8 * ADAPT);
                const float* xb = xs + (s * 8) * RSF + rg * 8;
                #pragma unroll
                for (int kk = 0; kk < 8; kk++) {
                    float4 w = *(const float4*)(wl + kk * ADAPT + tq * 4);
                    ulonglong2 x01 = *(const ulonglong2*)(xb + kk * RSF);
                    ulonglong2 x23 = *(const ulonglong2*)(xb + kk * RSF + 4);
                    ull W0, W1d, W2d, W3d;
                    PACK2(W0, w.x); PACK2(W1d, w.y); PACK2(W2d, w.z); PACK2(W3d, w.w);
                    FMA2(acc[0],  W0,  x01.x, acc[0]);  FMA2(acc[1],  W0,  x01.y, acc[1]);
                    FMA2(acc[2],  W0,  x23.x, acc[2]);  FMA2(acc[3],  W0,  x23.y, acc[3]);
                    FMA2(acc[4],  W1d, x01.x, acc[4]);  FMA2(acc[5],  W1d, x01.y, acc[5]);
                    FMA2(acc[6],  W1d, x23.x, acc[6]);  FMA2(acc[7],  W1d, x23.y, acc[7]);
                    FMA2(acc[8],  W2d, x01.x, acc[8]);  FMA2(acc[9],  W2d, x01.y, acc[9]);
                    FMA2(acc[10], W2d, x23.x, acc[10]); FMA2(acc[11], W2d, x23.y, acc[11]);
                    FMA2(acc[12], W3d, x01.x, acc[12]); FMA2(acc[13], W3d, x01.y, acc[13]);
                    FMA2(acc[14], W3d, x23.x, acc[14]); FMA2(acc[15], W3d, x23.y, acc[15]);
                }
            }
            if (++cons == RING) cons = 0;
            if (++prod == RING) prod = 0;
        }
        // epilogue: transpose in-register -> coalesced float4 per row
        #pragma unroll
        for (int rp = 0; rp < 4; rp++) {
            float4 ve, vo;
            UNPK2(ve.x, vo.x, acc[0  + rp]);
            UNPK2(ve.y, vo.y, acc[4  + rp]);
            UNPK2(ve.z, vo.z, acc[8  + rp]);
            UNPK2(ve.w, vo.w, acc[12 + rp]);
            int r0 = rg * 8 + rp * 2;
            if (r0 < nn)
                *(float4*)(hp + (size_t)rows[base + r0] * ADAPT + tq * 4) = ve;
            if (r0 + 1 < nn)
                *(float4*)(hp + (size_t)rows[base + r0 + 1] * ADAPT + tq * 4) = vo;
        }
    }
}

// ---------------------------------------------------------------------------
// GEMM2: out[row, d] = g_h[row,:] . W2[p,:,d] + b2[p,d]
// grid (64, 8), 128 thr. Same structure; d-quad tq, 8 rows per warp.
// ---------------------------------------------------------------------------
__global__ void __launch_bounds__(128, 5)
k_gemm2(const float* __restrict__ W2, const float* __restrict__ b2,
        float* __restrict__ out) {
    extern __shared__ __align__(16) char smx[];
    float* hs = (float*)smx;                      // [128 a][RSF] (18 KB)
    float* ws = (float*)(smx + ADAPT * RSF * 4);  // ring [6][8*128] (24 KB)
    int p  = blockIdx.x;
    int dc = blockIdx.y;
    int n = g_cnt[p];
    if (n == 0) return;
    int t  = threadIdx.x;
    int tq = t & 31;
    int rg = t >> 5;
    int js = t & 3;
    int rs = t >> 2;
    const int* rows = g_rows[p];
    const float* Wb = W2 + (size_t)p * ADAPT * D_MODEL + dc * DC;
    int d0 = dc * DC + tq * 4;
    float4 bias = *(const float4*)(b2 + (size_t)p * D_MODEL + d0);
    unsigned wsb = (unsigned)__cvta_generic_to_shared(ws);
    int wline = t >> 5;               // refill: lines (wline, wline+4), col = t&31
    int wcol  = t & 31;

    for (int base = 0; base < n; base += RT) {
        int nn = min(RT, n - base);
        __syncthreads();
        #pragma unroll
        for (int s = 0; s < RING - 1; s++) {
            CP16(wsb + s * 4096u + (unsigned)(wline * 32 + wcol) * 16u,
                 (const float4*)(Wb + (size_t)(s * 8 + wline) * D_MODEL) + wcol);
            CP16(wsb + s * 4096u + (unsigned)((wline + 4) * 32 + wcol) * 16u,
                 (const float4*)(Wb + (size_t)(s * 8 + wline + 4) * D_MODEL) + wcol);
            CPCOMMIT();
        }
        // stage h plain floats [a][row]
        {
            const float* hr = (rs < nn) ? g_h + (size_t)rows[base + rs] * ADAPT : 0;
            #pragma unroll
            for (int c = 0; c < 32; c++) {
                int a = js + 4 * c;
                hs[a * RSF + rs] = (rs < nn) ? hr[a] : 0.f;
            }
        }
        ull acc[16];
        #pragma unroll
        for (int j = 0; j < 16; j++) acc[j] = 0;
        bool active = (rg * 8 < nn);
        int cons = 0, prod = RING - 1;

        #pragma unroll 1
        for (int s = 0; s < NST; s++) {
            CPWAIT4();
            __syncthreads();
            if (s + RING - 1 < NST) {
                int sl = (s + RING - 1) * 8;
                CP16(wsb + prod * 4096u + (unsigned)(wline * 32 + wcol) * 16u,
                     (const float4*)(Wb + (size_t)(sl + wline) * D_MODEL) + wcol);
                CP16(wsb + prod * 4096u + (unsigned)((wline + 4) * 32 + wcol) * 16u,
                     (const float4*)(Wb + (size_t)(sl + wline + 4) * D_MODEL) + wcol);
            }
            CPCOMMIT();
            if (active) {
                const float* wl = ws + cons * (8 * DC);
                const float* hb = hs + (s * 8) * RSF + rg * 8;
                #pragma unroll
                for (int kk = 0; kk < 8; kk++) {
                    float4 w = *(const float4*)(wl + kk * DC + tq * 4);
                    ulonglong2 h01 = *(const ulonglong2*)(hb + kk * RSF);
                    ulonglong2 h23 = *(const ulonglong2*)(hb + kk * RSF + 4);
                    ull W0, W1d, W2d, W3d;
                    PACK2(W0, w.x); PACK2(W1d, w.y); PACK2(W2d, w.z); PACK2(W3d, w.w);
                    FMA2(acc[0],  W0,  h01.x, acc[0]);  FMA2(acc[1],  W0,  h01.y, acc[1]);
                    FMA2(acc[2],  W0,  h23.x, acc[2]);  FMA2(acc[3],  W0,  h23.y, acc[3]);
                    FMA2(acc[4],  W1d, h01.x, acc[4]);  FMA2(acc[5],  W1d, h01.y, acc[5]);
                    FMA2(acc[6],  W1d, h23.x, acc[6]);  FMA2(acc[7],  W1d, h23.y, acc[7]);
                    FMA2(acc[8],  W2d, h01.x, acc[8]);  FMA2(acc[9],  W2d, h01.y, acc[9]);
                    FMA2(acc[10], W2d, h23.x, acc[10]); FMA2(acc[11], W2d, h23.y, acc[11]);
                    FMA2(acc[12], W3d, h01.x, acc[12]); FMA2(acc[13], W3d, h01.y, acc[13]);
                    FMA2(acc[14], W3d, h23.x, acc[14]); FMA2(acc[15], W3d, h23.y, acc[15]);
                }
            }
            if (++cons == RING) cons = 0;
            if (++prod == RING) prod = 0;
        }
        #pragma unroll
        for (int rp = 0; rp < 4; rp++) {
            float4 ve, vo;
            UNPK2(ve.x, vo.x, acc[0  + rp]);
            UNPK2(ve.y, vo.y, acc[4  + rp]);
            UNPK2(ve.z, vo.z, acc[8  + rp]);
            UNPK2(ve.w, vo.w, acc[12 + rp]);
            ve.x += bias.x; ve.y += bias.y; ve.z += bias.z; ve.w += bias.w;
            vo.x += bias.x; vo.y += bias.y; vo.z += bias.z; vo.w += bias.w;
            int r0 = rg * 8 + rp * 2;
            if (r0 < nn)
                *(float4*)(out + (size_t)rows[base + r0] * D_MODEL + d0) = ve;
            if (r0 + 1 < nn)
                *(float4*)(out + (size_t)rows[base + r0 + 1] * D_MODEL + d0) = vo;
        }
    }
}

// ---------------------------------------------------------------------------
#define SMEM1 (KCH * RSF * 4 + RING * 8 * ADAPT * 4)   // 18432 + 24576 = 43008
#define SMEM2 (ADAPT * RSF * 4 + RING * 8 * DC * 4)    // 43008

extern "C" void kernel_launch(void* const* d_in, const int* in_sizes, int n_in,
                              void* d_out, int out_size) {
    const float* x   = (const float*)d_in[0];
    const int*   src = (const int*)d_in[1];
    const int*   tgt = (const int*)d_in[2];
    const float* W1  = (const float*)d_in[3];
    const float* b1  = (const float*)d_in[4];
    const float* W2  = (const float*)d_in[5];
    const float* b2  = (const float*)d_in[6];
    float* out = (float*)d_out;
    int B = in_sizes[1];  // 1024

    cudaFuncSetAttribute(k_gemm1, cudaFuncAttributeMaxDynamicSharedMemorySize, SMEM1);
    cudaFuncSetAttribute(k_gemm2, cudaFuncAttributeMaxDynamicSharedMemorySize, SMEM2);

    k_build<<<1, 1024>>>(src, tgt, B);
    k_copy<<<128, 256>>>(x, src, tgt, out, B);
    k_gemm1<<<dim3(NPAIR, KC), 128, SMEM1>>>(x, W1);
    k_act<<<256, 256>>>(src, tgt, b1);
    k_gemm2<<<dim3(NPAIR, 8), 128, SMEM2>>>(W2, b2, out);
}